// round 9
// baseline (speedup 1.0000x reference)
#include <cuda_runtime.h>
#include <math.h>
#include <stdint.h>

// ---------------------------------------------------------------------------
// Problem constants
// ---------------------------------------------------------------------------
#define BATCH   2
#define SEQ     2048
#define DMODEL  1024
#define NH      16
#define DH      64
#define DFFN    4096
#define ATT     256
#define ROWS    (BATCH * SEQ)   // 4096
#define LN_EPS  1e-5f
#define ATT_SCALE 0.022097086912079608f   // 1/sqrt(2048)

// tcgen05 only exists on the arch-accelerated ('a') targets.
#if defined(__CUDA_ARCH_FEAT_SM103_ALL) || defined(__CUDA_ARCH_FEAT_SM100_ALL) || defined(__CUDA_ARCH_FEAT_SM101_ALL)
#define HAS_TCGEN5 1
#else
#define HAS_TCGEN5 0
#endif

// ---------------------------------------------------------------------------
// Scratch (static device globals)
// ---------------------------------------------------------------------------
__device__ float g_Q  [ROWS * DMODEL];
__device__ float g_K  [ROWS * DMODEL];
__device__ float g_V  [ROWS * DMODEL];
__device__ float g_CTX[ROWS * DMODEL];
__device__ float g_SA [ROWS * DMODEL];
__device__ float g_X1 [ROWS * DMODEL];   // exact (residual path)
__device__ float g_X1r[ROWS * DMODEL];   // tf32-rounded (GEMM A operand)
__device__ float g_FF1[ROWS * DFFN];
__device__ float g_Xr [ROWS * DMODEL];   // tf32-rounded copy of x
__device__ float g_WTq[DMODEL * DMODEL]; // [N,K] transposed weights
__device__ float g_WTk[DMODEL * DMODEL];
__device__ float g_WTv[DMODEL * DMODEL];
__device__ float g_WTo[DMODEL * DMODEL];
__device__ float g_WT1[DFFN * DMODEL];
__device__ float g_WT2[DMODEL * DFFN];

// ---------------------------------------------------------------------------
// Helpers
// ---------------------------------------------------------------------------
__device__ __forceinline__ float tf32r(float x) {
    uint32_t u = __float_as_uint(x), r;
    asm("cvt.rna.tf32.f32 %0, %1;\n" : "=r"(r) : "r"(u));
    return __uint_as_float(r);
}

__device__ __forceinline__ uint32_t smem_u32(const void* p) {
    uint32_t a;
    asm("{ .reg .u64 x; cvta.to.shared.u64 x, %1; cvt.u32.u64 %0, x; }"
        : "=r"(a) : "l"(p));
    return a;
}

__device__ __forceinline__ void cp_async16(uint32_t dst, const void* src) {
    asm volatile("cp.async.cg.shared.global [%0], [%1], 16;\n"
                 :: "r"(dst), "l"(src));
}
__device__ __forceinline__ void cp_commit() {
    asm volatile("cp.async.commit_group;\n");
}
template <int N>
__device__ __forceinline__ void cp_wait() {
    asm volatile("cp.async.wait_group %0;\n" :: "n"(N));
}

#if HAS_TCGEN5
__device__ __forceinline__ uint32_t elect_one() {
    uint32_t pred;
    asm volatile("{\n\t.reg .pred p;\n\telect.sync _|p, 0xFFFFFFFF;\n\t"
                 "selp.b32 %0, 1, 0, p;\n\t}" : "=r"(pred));
    return pred;
}

// SW128 K-major smem descriptor
__device__ __forceinline__ uint64_t make_desc_sw128(uint32_t addr) {
    const uint64_t base =
        (uint64_t(2)  << 61) | (uint64_t(1) << 46) |
        (uint64_t(64) << 32) | (uint64_t(1) << 16);
    return base | ((uint64_t)(addr >> 4) & 0x3FFF);
}

// idesc: dtype=F32(1<<4), a=TF32(2<<7), b=TF32(2<<10), N=128(16<<17), M=128(8<<24)
#define IDESC_TF32 0x8200910u

__device__ __forceinline__ void mma_ss_tf32(
    uint32_t d_tmem, uint64_t a_desc, uint64_t b_desc, uint32_t en)
{
    uint32_t z = 0;
    asm volatile(
        "{\n\t.reg .pred p;\n\tsetp.ne.u32 p, %5, 0;\n\t"
        "tcgen05.mma.cta_group::1.kind::tf32 [%0], %1, %2, %3, {%4,%4,%4,%4}, p;\n\t}"
        :: "r"(d_tmem), "l"(a_desc), "l"(b_desc), "r"(IDESC_TF32),
           "r"(z), "r"(en)
        : "memory");
}

__device__ __forceinline__ void mbar_wait(uint32_t mb, uint32_t parity) {
    uint32_t done;
    asm volatile(
        "{\n\t.reg .pred p;\n\t"
        "mbarrier.try_wait.parity.acquire.cta.shared::cta.b64 p, [%1], %2;\n\t"
        "selp.b32 %0, 1, 0, p;\n\t}"
        : "=r"(done) : "r"(mb), "r"(parity) : "memory");
    if (!done) {
        asm volatile(
            "{\n\t.reg .pred P1;\n\t"
            "WAIT_LOOP_%=:\n\t"
            "mbarrier.try_wait.parity.acquire.cta.shared::cta.b64 P1, [%0], %1, 0x989680;\n\t"
            "@P1 bra.uni WAIT_DONE_%=;\n\t"
            "bra.uni WAIT_LOOP_%=;\n\t"
            "WAIT_DONE_%=:\n\t}"
            :: "r"(mb), "r"(parity) : "memory");
    }
}

__device__ __forceinline__ void ldtm_x32(uint32_t* r, uint32_t tmem_addr) {
    asm volatile(
        "tcgen05.ld.sync.aligned.32x32b.x32.b32 "
        "{%0, %1, %2, %3, %4, %5, %6, %7, "
        " %8, %9, %10, %11, %12, %13, %14, %15, "
        " %16, %17, %18, %19, %20, %21, %22, %23, "
        " %24, %25, %26, %27, %28, %29, %30, %31}, [%32];"
        : "=r"(r[0]),  "=r"(r[1]),  "=r"(r[2]),  "=r"(r[3]),
          "=r"(r[4]),  "=r"(r[5]),  "=r"(r[6]),  "=r"(r[7]),
          "=r"(r[8]),  "=r"(r[9]),  "=r"(r[10]), "=r"(r[11]),
          "=r"(r[12]), "=r"(r[13]), "=r"(r[14]), "=r"(r[15]),
          "=r"(r[16]), "=r"(r[17]), "=r"(r[18]), "=r"(r[19]),
          "=r"(r[20]), "=r"(r[21]), "=r"(r[22]), "=r"(r[23]),
          "=r"(r[24]), "=r"(r[25]), "=r"(r[26]), "=r"(r[27]),
          "=r"(r[28]), "=r"(r[29]), "=r"(r[30]), "=r"(r[31])
        : "r"(tmem_addr));
}
#endif  // HAS_TCGEN5

// ---------------------------------------------------------------------------
// GEMM: C[M,N] = A[M,K] @ BT[N,K]^T + bias (+GELU) (+tf32 round of output)
// CTA tile 128x256 (TWO 128-col TMEM accumulator chains), 256 threads,
// BK=32 (128-byte K-major rows = SW128 atom), FOUR-stage cp.async pipeline
// (prefetch(it+3) reuses the stage of it-1 -> 2 iterations of slack).
// ---------------------------------------------------------------------------
#define TILE_A  16384                       // 128 x 128B
#define TILE_BB 32768                       // 256 x 128B (two 128-row tiles)
#define STAGE_B (TILE_A + TILE_BB)          // 49152
#define NSTAGE  4
#define GEMM_SMEM (1024 + NSTAGE * STAGE_B) // 197632 bytes

template <int GELU, int ROUND>
__global__ __launch_bounds__(256) void gemm_tc(
    const float* __restrict__ A, const float* __restrict__ BT,
    const float* __restrict__ bias, float* __restrict__ C,
    int M, int N, int K)
{
    extern __shared__ __align__(1024) char smem[];
    const uint32_t sb = smem_u32(smem);
    const int tid = threadIdx.x;
    const int wid = tid >> 5;
    const int lid = tid & 31;
    const int m0 = blockIdx.y * 128;
    const int n0 = blockIdx.x * 256;

    const float* Ag = A + (size_t)m0 * K;
    const float* Bg = BT + (size_t)n0 * K;

    auto prefetch = [&](int it, int stage) {
        const int k0 = it * 32;
        const uint32_t abase = sb + 1024 + stage * STAGE_B;
        const uint32_t bbase = abase + TILE_A;
        // A: 1024 16B chunks (128 rows x 8)
        #pragma unroll
        for (int j = 0; j < 4; j++) {
            const int ch = j * 256 + tid;
            const int r  = ch >> 3;
            const int c  = ch & 7;
            const uint32_t off = r * 128 + c * 16;
            const uint32_t sw  = off ^ ((off >> 3) & 0x70);
            cp_async16(abase + sw, Ag + (size_t)r * K + k0 + c * 4);
        }
        // B: 2048 chunks (256 rows x 8); rows 0-127 -> tile0, 128-255 -> tile1
        #pragma unroll
        for (int j = 0; j < 8; j++) {
            const int ch = j * 256 + tid;
            const int r  = ch >> 3;          // 0..255
            const int c  = ch & 7;
            const uint32_t off = (r & 127) * 128 + c * 16;
            const uint32_t sw  = (off ^ ((off >> 3) & 0x70)) + (r >> 7) * TILE_A * 0 + (uint32_t)(r >> 7) * 16384u;
            cp_async16(bbase + sw, Bg + (size_t)r * K + k0 + c * 4);
        }
        cp_commit();
    };

    const int nIter = K / 32;

#if HAS_TCGEN5
    // ---------------- tcgen05 path ----------------
    if (wid == 0) {
        asm volatile(
            "tcgen05.alloc.cta_group::1.sync.aligned.shared::cta.b32 [%0], %1;"
            :: "r"(sb + 0), "r"(512u) : "memory");
        asm volatile("tcgen05.relinquish_alloc_permit.cta_group::1.sync.aligned;");
    }
    if (tid == 0) {
        asm volatile("mbarrier.init.shared.b64 [%0], %1;" :: "r"(sb + 8),  "r"(1u) : "memory");
        asm volatile("mbarrier.init.shared.b64 [%0], %1;" :: "r"(sb + 16), "r"(1u) : "memory");
        asm volatile("mbarrier.init.shared.b64 [%0], %1;" :: "r"(sb + 24), "r"(1u) : "memory");
        asm volatile("mbarrier.init.shared.b64 [%0], %1;" :: "r"(sb + 32), "r"(1u) : "memory");
    }
    __syncthreads();

    uint32_t tmem;
    asm volatile("ld.shared.b32 %0, [%1];" : "=r"(tmem) : "r"(sb + 0));

    prefetch(0, 0);
    prefetch(1, 1);
    prefetch(2, 2);

    int cnt0 = 0, cnt1 = 0, cnt2 = 0, cnt3 = 0;

    for (int it = 0; it < nIter; it++) {
        const int s = it & 3;
        const int remaining = nIter - 1 - it;
        if (remaining >= 2) cp_wait<2>();
        else if (remaining == 1) cp_wait<1>();
        else cp_wait<0>();
        __syncthreads();

        if (wid == 0 && elect_one()) {
            asm volatile("fence.proxy.async.shared::cta;" ::: "memory");
            const uint32_t stb = sb + 1024 + s * STAGE_B;
            const uint64_t ad  = make_desc_sw128(stb);
            const uint64_t bd0 = make_desc_sw128(stb + TILE_A);
            const uint64_t bd1 = make_desc_sw128(stb + TILE_A + 16384);
            #pragma unroll
            for (int c = 0; c < 4; c++) {
                const uint32_t en = (it > 0 || c > 0) ? 1u : 0u;
                mma_ss_tf32(tmem,       ad + c * 2, bd0 + c * 2, en);
                mma_ss_tf32(tmem + 128, ad + c * 2, bd1 + c * 2, en);
            }
            asm volatile(
                "tcgen05.commit.cta_group::1.mbarrier::arrive::one.shared::cluster.b64 [%0];"
                :: "r"(sb + 8 + s * 8) : "memory");
        }

        if (it + 3 < nIter) {
            const int ws = (it + 3) & 3;     // stage last used by iter it-1
            if (it >= 1) {
                switch (ws) {
                    case 0: mbar_wait(sb + 8,  cnt0 & 1); cnt0++; break;
                    case 1: mbar_wait(sb + 16, cnt1 & 1); cnt1++; break;
                    case 2: mbar_wait(sb + 24, cnt2 & 1); cnt2++; break;
                    default: mbar_wait(sb + 32, cnt3 & 1); cnt3++; break;
                }
            }
            prefetch(it + 3, ws);
        }
    }
    {   // wait for the final commit: covers all prior MMAs (FIFO order)
        const int ls = (nIter - 1) & 3;
        switch (ls) {
            case 0: mbar_wait(sb + 8,  cnt0 & 1); cnt0++; break;
            case 1: mbar_wait(sb + 16, cnt1 & 1); cnt1++; break;
            case 2: mbar_wait(sb + 24, cnt2 & 1); cnt2++; break;
            default: mbar_wait(sb + 32, cnt3 & 1); cnt3++; break;
        }
    }
    asm volatile("tcgen05.fence::after_thread_sync;" ::: "memory");

    // epilogue: warps 0-3 -> D0 (cols n0..n0+127); warps 4-7 -> D1 (+128)
    {
        const int dsel = wid >> 2;                   // 0 or 1
        const int subw = wid & 3;
        const int row  = m0 + subw * 32 + lid;
        const int cb   = n0 + dsel * 128;
        const uint32_t tbase = tmem + dsel * 128;
        float* Crow = C + (size_t)row * N + cb;
        #pragma unroll
        for (int base = 0; base < 128; base += 32) {
            uint32_t dr[32];
            ldtm_x32(dr, tbase + base);
            asm volatile("tcgen05.wait::ld.sync.aligned;" ::: "memory");
            float v[32];
            #pragma unroll
            for (int c = 0; c < 32; c++) {
                float t = __uint_as_float(dr[c]) + bias[cb + base + c];
                if (GELU)
                    t = 0.5f * t * (1.0f + erff(t * 0.7071067811865475f));
                if (ROUND) t = tf32r(t);
                v[c] = t;
            }
            #pragma unroll
            for (int c = 0; c < 32; c += 4)
                *(float4*)(Crow + base + c) =
                    make_float4(v[c], v[c+1], v[c+2], v[c+3]);
        }
    }
    asm volatile("tcgen05.fence::before_thread_sync;" ::: "memory");

    __syncthreads();
    if (tid == 0) {
        asm volatile("mbarrier.inval.shared.b64 [%0];" :: "r"(sb + 8)  : "memory");
        asm volatile("mbarrier.inval.shared.b64 [%0];" :: "r"(sb + 16) : "memory");
        asm volatile("mbarrier.inval.shared.b64 [%0];" :: "r"(sb + 24) : "memory");
        asm volatile("mbarrier.inval.shared.b64 [%0];" :: "r"(sb + 32) : "memory");
    }
    __syncthreads();
    if (wid == 0)
        asm volatile("tcgen05.dealloc.cta_group::1.sync.aligned.b32 %0, %1;"
                     :: "r"(tmem), "r"(512u));

#else
    // ---------------- FFMA fallback (non-'a' targets) ----------------
    const int ty = tid >> 5;   // 0..7  -> rows ty*16 .. +15
    const int tx = tid & 31;   // 0..31 -> cols tx*8 .. +7

    float acc[16][8];
    #pragma unroll
    for (int i = 0; i < 16; i++)
        #pragma unroll
        for (int j = 0; j < 8; j++) acc[i][j] = 0.f;

    prefetch(0, 0);
    prefetch(1, 1);
    prefetch(2, 2);

    for (int it = 0; it < nIter; it++) {
        const int s = it & 3;
        const int remaining = nIter - 1 - it;
        if (remaining >= 2) cp_wait<2>();
        else if (remaining == 1) cp_wait<1>();
        else cp_wait<0>();
        __syncthreads();

        const char* ab = smem + 1024 + s * STAGE_B;
        const char* bb = ab + TILE_A;

        #pragma unroll 4
        for (int kk = 0; kk < 32; kk++) {
            float a[16], b[8];
            #pragma unroll
            for (int i = 0; i < 16; i++) {
                const uint32_t off = (ty * 16 + i) * 128 + kk * 4;
                a[i] = *(const float*)(ab + (off ^ ((off >> 3) & 0x70)));
            }
            #pragma unroll
            for (int j = 0; j < 8; j++) {
                const int col = tx * 8 + j;
                const uint32_t off = (col & 127) * 128 + kk * 4;
                b[j] = *(const float*)(bb + (col >> 7) * 16384 +
                                       (off ^ ((off >> 3) & 0x70)));
            }
            #pragma unroll
            for (int i = 0; i < 16; i++)
                #pragma unroll
                for (int j = 0; j < 8; j++)
                    acc[i][j] += a[i] * b[j];
        }
        __syncthreads();
        if (it + 3 < nIter) prefetch(it + 3, (it + 3) & 3);
    }

    #pragma unroll
    for (int i = 0; i < 16; i++) {
        const int row = m0 + ty * 16 + i;
        float* Crow = C + (size_t)row * N + n0 + tx * 8;
        float v[8];
        #pragma unroll
        for (int j = 0; j < 8; j++) {
            float t = acc[i][j] + bias[n0 + tx * 8 + j];
            if (GELU)
                t = 0.5f * t * (1.0f + erff(t * 0.7071067811865475f));
            if (ROUND) t = tf32r(t);
            v[j] = t;
        }
        *(float4*)(Crow)     = make_float4(v[0], v[1], v[2], v[3]);
        *(float4*)(Crow + 4) = make_float4(v[4], v[5], v[6], v[7]);
    }
#endif
}

// ---------------------------------------------------------------------------
// Weight transpose + tf32 round: out[n][k] = rna_tf32(in[k][n]); in [K,N]
// ---------------------------------------------------------------------------
__global__ __launch_bounds__(256) void transpose_round(
    const float* __restrict__ in, float* __restrict__ out, int K, int N)
{
    __shared__ float t[32][33];
    const int x0 = blockIdx.x * 32;
    const int y0 = blockIdx.y * 32;
    const int tx = threadIdx.x;
    const int ty = threadIdx.y;
    #pragma unroll
    for (int j = 0; j < 32; j += 8)
        t[ty + j][tx] = in[(size_t)(y0 + ty + j) * N + x0 + tx];
    __syncthreads();
    #pragma unroll
    for (int j = 0; j < 32; j += 8)
        out[(size_t)(x0 + ty + j) * K + y0 + tx] = tf32r(t[tx][ty + j]);
}

__global__ __launch_bounds__(256) void round_copy(
    const float* __restrict__ in, float* __restrict__ out, int n4)
{
    int i = blockIdx.x * blockDim.x + threadIdx.x;
    if (i < n4) {
        float4 v = ((const float4*)in)[i];
        v.x = tf32r(v.x); v.y = tf32r(v.y);
        v.z = tf32r(v.z); v.w = tf32r(v.w);
        ((float4*)out)[i] = v;
    }
}

// ---------------------------------------------------------------------------
// Banded attention, 4 threads per query (16 channels each), 256-thread blocks.
// ---------------------------------------------------------------------------
__global__ __launch_bounds__(256) void attn_kernel(
    const float* __restrict__ Q, const float* __restrict__ Km,
    const float* __restrict__ Vm, float* __restrict__ CTX)
{
    __shared__ float4 Ks[64][16];
    __shared__ float4 Vs[64][16];

    const int tid = threadIdx.x;
    const int qi  = tid >> 2;
    const int c   = tid & 3;
    const int i0  = blockIdx.x * 64;
    const int h   = blockIdx.y;
    const int b   = blockIdx.z;
    const int i   = i0 + qi;

    const size_t qoff = ((size_t)(b * SEQ + i) * DMODEL) + h * DH + c * 16;

    float4 q[4], o[4];
    #pragma unroll
    for (int cc = 0; cc < 4; cc++) {
        q[cc] = *(const float4*)(Q + qoff + cc * 4);
        o[cc] = make_float4(0.f, 0.f, 0.f, 0.f);
    }
    float l = 0.f;

    const int jlo = max(0, i0 - ATT);
    const int jhi = min(SEQ, i0 + 64 + ATT);

    for (int jt = jlo; jt < jhi; jt += 64) {
        for (int idx = tid; idx < 64 * 16; idx += 256) {
            const int row = idx >> 4;
            const int c4  = idx & 15;
            const size_t off =
                ((size_t)(b * SEQ + jt + row) * DMODEL) + h * DH + c4 * 4;
            Ks[row][c4] = *(const float4*)(Km + off);
            Vs[row][c4] = *(const float4*)(Vm + off);
        }
        __syncthreads();

        #pragma unroll 4
        for (int jj = 0; jj < 64; jj++) {
            const int j = jt + jj;
            float s = 0.f;
            #pragma unroll
            for (int cc = 0; cc < 4; cc++) {
                float4 kv = Ks[jj][c * 4 + cc];
                s += q[cc].x * kv.x + q[cc].y * kv.y
                   + q[cc].z * kv.z + q[cc].w * kv.w;
            }
            s += __shfl_xor_sync(0xffffffffu, s, 1);
            s += __shfl_xor_sync(0xffffffffu, s, 2);
            const bool inband = ((i - j) <= ATT) && ((j - i) <= ATT);
            const float p = inband ? __expf(s * ATT_SCALE) : 0.f;
            l += p;
            #pragma unroll
            for (int cc = 0; cc < 4; cc++) {
                float4 vv = Vs[jj][c * 4 + cc];
                o[cc].x += p * vv.x; o[cc].y += p * vv.y;
                o[cc].z += p * vv.z; o[cc].w += p * vv.w;
            }
        }
        __syncthreads();
    }

    const float inv = 1.f / l;
    #pragma unroll
    for (int cc = 0; cc < 4; cc++) {
        *(float4*)(CTX + qoff + cc * 4) =
            make_float4(tf32r(o[cc].x * inv), tf32r(o[cc].y * inv),
                        tf32r(o[cc].z * inv), tf32r(o[cc].w * inv));
    }
}

// ---------------------------------------------------------------------------
// Residual add + LayerNorm; optionally writes a second tf32-rounded copy.
// ---------------------------------------------------------------------------
template <int DUAL>
__global__ __launch_bounds__(256) void add_ln_kernel(
    const float* __restrict__ A, const float* __restrict__ R,
    const float* __restrict__ gamma, const float* __restrict__ beta,
    float* __restrict__ out, float* __restrict__ out_r)
{
    __shared__ float red1[8];
    __shared__ float red2[8];

    const int row = blockIdx.x;
    const int t   = threadIdx.x;
    const size_t off = (size_t)row * DMODEL;

    float4 a = *(const float4*)(A + off + t * 4);
    float4 r = *(const float4*)(R + off + t * 4);
    float x0 = a.x + r.x, x1 = a.y + r.y, x2 = a.z + r.z, x3 = a.w + r.w;

    float s = x0 + x1 + x2 + x3;
    #pragma unroll
    for (int oo = 16; oo; oo >>= 1) s += __shfl_xor_sync(0xffffffffu, s, oo);
    if ((t & 31) == 0) red1[t >> 5] = s;
    __syncthreads();

    float mu = 0.f;
    #pragma unroll
    for (int w = 0; w < 8; w++) mu += red1[w];
    mu *= (1.f / DMODEL);

    float d0 = x0 - mu, d1 = x1 - mu, d2 = x2 - mu, d3 = x3 - mu;
    float ss = d0 * d0 + d1 * d1 + d2 * d2 + d3 * d3;
    #pragma unroll
    for (int oo = 16; oo; oo >>= 1) ss += __shfl_xor_sync(0xffffffffu, ss, oo);
    if ((t & 31) == 0) red2[t >> 5] = ss;
    __syncthreads();

    float var = 0.f;
    #pragma unroll
    for (int w = 0; w < 8; w++) var += red2[w];
    var *= (1.f / DMODEL);

    const float rstd = rsqrtf(var + LN_EPS);

    float4 gm = *(const float4*)(gamma + t * 4);
    float4 bb = *(const float4*)(beta + t * 4);
    float y0 = d0 * rstd * gm.x + bb.x;
    float y1 = d1 * rstd * gm.y + bb.y;
    float y2 = d2 * rstd * gm.z + bb.z;
    float y3 = d3 * rstd * gm.w + bb.w;
    *(float4*)(out + off + t * 4) = make_float4(y0, y1, y2, y3);
    if (DUAL) {
        *(float4*)(out_r + off + t * 4) =
            make_float4(tf32r(y0), tf32r(y1), tf32r(y2), tf32r(y3));
    }
}

// ---------------------------------------------------------------------------
// Launcher  (order arranged so GEMM-Q is launch index 5 -> ncu profiles it)
// ---------------------------------------------------------------------------
extern "C" void kernel_launch(void* const* d_in, const int* in_sizes, int n_in,
                              void* d_out, int out_size)
{
    const float* x    = (const float*)d_in[0];
    const float* Wq   = (const float*)d_in[1];
    const float* bq   = (const float*)d_in[2];
    const float* Wk   = (const float*)d_in[3];
    const float* bk   = (const float*)d_in[4];
    const float* Wv   = (const float*)d_in[5];
    const float* bv   = (const float*)d_in[6];
    const float* Wo   = (const float*)d_in[7];
    const float* bo   = (const float*)d_in[8];
    const float* W1   = (const float*)d_in[9];
    const float* b1   = (const float*)d_in[10];
    const float* W2   = (const float*)d_in[11];
    const float* b2   = (const float*)d_in[12];
    const float* ln1g = (const float*)d_in[13];
    const float* ln1b = (const float*)d_in[14];
    const float* ln2g = (const float*)d_in[15];
    const float* ln2b = (const float*)d_in[16];
    float* out = (float*)d_out;

    float *Qp, *Kp, *Vp, *CTXp, *SAp, *X1p, *X1rp, *FF1p, *Xrp;
    float *WTq, *WTk, *WTv, *WTo, *WT1, *WT2;
    cudaGetSymbolAddress((void**)&Qp,   g_Q);
    cudaGetSymbolAddress((void**)&Kp,   g_K);
    cudaGetSymbolAddress((void**)&Vp,   g_V);
    cudaGetSymbolAddress((void**)&CTXp, g_CTX);
    cudaGetSymbolAddress((void**)&SAp,  g_SA);
    cudaGetSymbolAddress((void**)&X1p,  g_X1);
    cudaGetSymbolAddress((void**)&X1rp, g_X1r);
    cudaGetSymbolAddress((void**)&FF1p, g_FF1);
    cudaGetSymbolAddress((void**)&Xrp,  g_Xr);
    cudaGetSymbolAddress((void**)&WTq,  g_WTq);
    cudaGetSymbolAddress((void**)&WTk,  g_WTk);
    cudaGetSymbolAddress((void**)&WTv,  g_WTv);
    cudaGetSymbolAddress((void**)&WTo,  g_WTo);
    cudaGetSymbolAddress((void**)&WT1,  g_WT1);
    cudaGetSymbolAddress((void**)&WT2,  g_WT2);

    cudaFuncSetAttribute(gemm_tc<0,0>,
        cudaFuncAttributeMaxDynamicSharedMemorySize, GEMM_SMEM);
    cudaFuncSetAttribute(gemm_tc<0,1>,
        cudaFuncAttributeMaxDynamicSharedMemorySize, GEMM_SMEM);
    cudaFuncSetAttribute(gemm_tc<1,1>,
        cudaFuncAttributeMaxDynamicSharedMemorySize, GEMM_SMEM);

    dim3 tb(32, 8);
    // launches 0-4
    transpose_round<<<dim3(DMODEL/32, DMODEL/32), tb>>>(Wq, WTq, DMODEL, DMODEL);
    transpose_round<<<dim3(DMODEL/32, DMODEL/32), tb>>>(Wk, WTk, DMODEL, DMODEL);
    transpose_round<<<dim3(DMODEL/32, DMODEL/32), tb>>>(Wv, WTv, DMODEL, DMODEL);
    transpose_round<<<dim3(DMODEL/32, DMODEL/32), tb>>>(Wo, WTo, DMODEL, DMODEL);
    round_copy<<<(ROWS * DMODEL / 4 + 255) / 256, 256>>>(x, Xrp, ROWS * DMODEL / 4);

    dim3 gD(DMODEL / 256, ROWS / 128);   // (4, 32) = 128 CTAs
    dim3 gF(DFFN / 256,   ROWS / 128);   // (16, 32) = 512 CTAs

    // launch 5 -> profiled by ncu (-s 5 -c 1)
    gemm_tc<0,0><<<gD, 256, GEMM_SMEM>>>(Xrp, WTq, bq, Qp, ROWS, DMODEL, DMODEL);
    gemm_tc<0,0><<<gD, 256, GEMM_SMEM>>>(Xrp, WTk, bk, Kp, ROWS, DMODEL, DMODEL);
    gemm_tc<0,0><<<gD, 256, GEMM_SMEM>>>(Xrp, WTv, bv, Vp, ROWS, DMODEL, DMODEL);

    dim3 ag(SEQ / 64, NH, BATCH);
    attn_kernel<<<ag, 256>>>(Qp, Kp, Vp, CTXp);

    // FFN weight transposes (independent; placed late to keep GEMM-Q at #5)
    transpose_round<<<dim3(DFFN/32,   DMODEL/32), tb>>>(W1, WT1, DMODEL, DFFN);
    transpose_round<<<dim3(DMODEL/32, DFFN/32),   tb>>>(W2, WT2, DFFN, DMODEL);

    gemm_tc<0,0><<<gD, 256, GEMM_SMEM>>>(CTXp, WTo, bo, SAp, ROWS, DMODEL, DMODEL);
    add_ln_kernel<1><<<ROWS, 256>>>(SAp, x, ln1g, ln1b, X1p, X1rp);

    gemm_tc<1,1><<<gF, 256, GEMM_SMEM>>>(X1rp, WT1, b1, FF1p, ROWS, DFFN, DMODEL);
    gemm_tc<0,0><<<gD, 256, GEMM_SMEM>>>(FF1p, WT2, b2, SAp, ROWS, DMODEL, DFFN);
    add_ln_kernel<0><<<ROWS, 256>>>(SAp, X1p, ln2g, ln2b, out, nullptr);
}